// round 16
// baseline (speedup 1.0000x reference)
#include <cuda_runtime.h>
#include <cuda_bf16.h>
#include <cstdint>

// Problem constants (fixed by setup_inputs)
#define NB 16      // batch
#define LL 512     // sequence length
#define DD 256     // encoder dim = filter size
#define TT 4096    // WVF_max_length
#define TP 32      // L-positions per conv block
#define XSS 260    // xs smem row stride (pad: 260%32=4 -> conflict-free frags)

// Intermediates (no cudaMalloc allowed) — referenced directly from device code.
__device__ float g_h1[NB * LL * DD];    // fp32 h1 (split to tf32 hi/lo on load)
__device__ int   g_dur[NB * LL];
__device__ int   g_lmap[NB * TT];
// Fragment-packed weights: [kk][c][tile][lane] float4 = (bhi0,bhi1,blo0,blo1)
//   b0 = w[kk][8c + lane%4    ][8*tile + lane/4]
//   b1 = w[kk][8c + lane%4 + 4][8*tile + lane/4]
__device__ float4 g_wf1[3 * 32 * 32 * 32];
__device__ float4 g_wf2[3 * 32 * 32 * 32];

// ---- tf32 helpers ----
__device__ __forceinline__ unsigned f2tf32(float v)
{
    unsigned r;
    asm("cvt.rna.tf32.f32 %0, %1;" : "=r"(r) : "f"(v));
    return r;
}

// m16n8k8 tf32 MMA, C += A*B (C in-place)
__device__ __forceinline__ void mma_tf32(float* c,
                                         unsigned a0, unsigned a1,
                                         unsigned a2, unsigned a3,
                                         unsigned b0, unsigned b1)
{
    asm("mma.sync.aligned.m16n8k8.row.col.f32.tf32.tf32.f32 "
        "{%0,%1,%2,%3},{%4,%5,%6,%7},{%8,%9},{%0,%1,%2,%3};"
        : "+f"(c[0]), "+f"(c[1]), "+f"(c[2]), "+f"(c[3])
        : "r"(a0), "r"(a1), "r"(a2), "r"(a3), "r"(b0), "r"(b1));
}

// ---------------------------------------------------------------------------
// Prep: pack weights into B-fragment order with tf32 hi/lo.
// grid = 2 layers * 3 kk * 32 c;  block = 1024 (tile = tid/32, lane = tid%32)
// ---------------------------------------------------------------------------
__global__ void __launch_bounds__(1024) pack_wf_kernel(
    const float* __restrict__ w1, const float* __restrict__ w2)
{
    const int b = blockIdx.x;
    const int layer = b / 96;
    const int kk = (b % 96) / 32;
    const int c = b % 32;
    const int tile = threadIdx.x >> 5;
    const int lane = threadIdx.x & 31;
    const int t = lane & 3;
    const int g = lane >> 2;
    const int f = tile * 8 + g;
    const float* src = (layer == 0) ? w1 : w2;
    float4* dst = (layer == 0) ? g_wf1 : g_wf2;

    const float w0 = src[kk * (DD * 256) + (8 * c + t) * 256 + f];
    const float w1v = src[kk * (DD * 256) + (8 * c + t + 4) * 256 + f];
    const unsigned h0 = f2tf32(w0);
    const unsigned h1 = f2tf32(w1v);
    const unsigned l0 = f2tf32(w0 - __uint_as_float(h0));
    const unsigned l1 = f2tf32(w1v - __uint_as_float(h1));
    dst[((kk * 32 + c) * 32 + tile) * 32 + lane] =
        make_float4(__uint_as_float(h0), __uint_as_float(h1),
                    __uint_as_float(l0), __uint_as_float(l1));
}

// ---------------------------------------------------------------------------
// Fused conv1d(K=3) via 3xTF32 warp-MMA + bias + LayerNorm(F) + ReLU
// STAGE 0: src = x (fp32),  dst = g_h1 (fp32)
// STAGE 1: src = g_h1 (fp32), fused linear head -> g_dur
// Block = 32 l x 256 f, 8 warps. NEW layout: each warp owns a 32-f subtile
// (wid*32..wid*32+31) across the FULL M=32 (two A fragment sets) -> zero
// cross-warp B duplication; B LDG per warp halved vs 2x4 layout.
// Dynamic smem: xs_hi[34][260] | xs_lo[34][260]; hs (32x256) aliases xs_hi.
// ---------------------------------------------------------------------------
#define SMEM_BYTES (2 * 34 * XSS * 4)   // 70720

template<int STAGE>
__global__ void __launch_bounds__(256, 2) conv_ln_relu_kernel(
    const float* __restrict__ x,
    const float* __restrict__ bias,
    const float* __restrict__ gamma,
    const float* __restrict__ beta,
    const float* __restrict__ lin_w,
    const float* __restrict__ lin_b)
{
    extern __shared__ float smem[];
    float* xs_hi = smem;                  // [34][XSS]
    float* xs_lo = smem + 34 * XSS;       // [34][XSS]
    float* hs    = smem;                  // [32][256], reused after mainloop
    __shared__ float mu_s[TP];
    __shared__ float rs_s[TP];

    const float* __restrict__ src = (STAGE == 0) ? x : (const float*)g_h1;
    const float4* __restrict__ wfb = (STAGE == 0) ? g_wf1 : g_wf2;

    const int blk = blockIdx.x;
    const int n   = blk / (LL / TP);
    const int l0  = (blk % (LL / TP)) * TP;
    const int f   = threadIdx.x;
    const int wid = f >> 5, lane = f & 31;

    // Load input rows, splitting to tf32 hi/lo inline (zero pad at edges)
    #pragma unroll
    for (int r = 0; r < TP + 2; r++) {
        int l = l0 - 1 + r;
        float v = (l >= 0 && l < LL) ? src[(n * LL + l) * DD + f] : 0.f;
        const float hf = __uint_as_float(f2tf32(v));
        xs_hi[r * XSS + f] = hf;
        xs_lo[r * XSS + f] = __uint_as_float(f2tf32(v - hf));
    }
    __syncthreads();

    // C fragments: 2 m-halves x 4 n8-tiles x 4 regs = 32 floats
    float cacc[2][4][4];
    #pragma unroll
    for (int h = 0; h < 2; h++)
        #pragma unroll
        for (int tl = 0; tl < 4; tl++)
            #pragma unroll
            for (int j = 0; j < 4; j++) cacc[h][tl][j] = 0.f;

    const int g = lane >> 2;           // fragment group id
    const int t = lane & 3;            // thread-in-group

    // Mainloop over K = 3 taps x 256 d (8 per MMA step)
    #pragma unroll 1
    for (int kk = 0; kk < 3; kk++) {
        const float* xh0 = xs_hi + (g + kk) * XSS + t;        // m-half 0: rows g, g+8
        const float* xl0 = xs_lo + (g + kk) * XSS + t;
        const float* xh1 = xs_hi + (16 + g + kk) * XSS + t;   // m-half 1: rows 16+g, 24+g
        const float* xl1 = xs_lo + (16 + g + kk) * XSS + t;
        #pragma unroll 2
        for (int c = 0; c < 32; c++) {
            const int d0 = 8 * c;
            // A fragments (row-major 16x8) for both m-halves, hi and lo
            const unsigned ah0[4] = {
                __float_as_uint(xh0[d0]), __float_as_uint(xh0[8 * XSS + d0]),
                __float_as_uint(xh0[d0 + 4]), __float_as_uint(xh0[8 * XSS + d0 + 4]) };
            const unsigned al0[4] = {
                __float_as_uint(xl0[d0]), __float_as_uint(xl0[8 * XSS + d0]),
                __float_as_uint(xl0[d0 + 4]), __float_as_uint(xl0[8 * XSS + d0 + 4]) };
            const unsigned ah1[4] = {
                __float_as_uint(xh1[d0]), __float_as_uint(xh1[8 * XSS + d0]),
                __float_as_uint(xh1[d0 + 4]), __float_as_uint(xh1[8 * XSS + d0 + 4]) };
            const unsigned al1[4] = {
                __float_as_uint(xl1[d0]), __float_as_uint(xl1[8 * XSS + d0]),
                __float_as_uint(xl1[d0 + 4]), __float_as_uint(xl1[8 * XSS + d0 + 4]) };

            // 4 B fragments for this warp's 32-f subtile (tiles wid*4 .. wid*4+3)
            const float4* bp = wfb + ((kk * 32 + c) * 1024) + (wid * 4) * 32 + lane;
            float4 b[4];
            #pragma unroll
            for (int tl = 0; tl < 4; tl++) b[tl] = bp[tl * 32];

            // Split-major issue: 8 independent accumulators per group
            #pragma unroll
            for (int tl = 0; tl < 4; tl++) {
                mma_tf32(cacc[0][tl], ah0[0], ah0[1], ah0[2], ah0[3],
                         __float_as_uint(b[tl].x), __float_as_uint(b[tl].y));
                mma_tf32(cacc[1][tl], ah1[0], ah1[1], ah1[2], ah1[3],
                         __float_as_uint(b[tl].x), __float_as_uint(b[tl].y));
            }
            #pragma unroll
            for (int tl = 0; tl < 4; tl++) {
                mma_tf32(cacc[0][tl], ah0[0], ah0[1], ah0[2], ah0[3],
                         __float_as_uint(b[tl].z), __float_as_uint(b[tl].w));
                mma_tf32(cacc[1][tl], ah1[0], ah1[1], ah1[2], ah1[3],
                         __float_as_uint(b[tl].z), __float_as_uint(b[tl].w));
            }
            #pragma unroll
            for (int tl = 0; tl < 4; tl++) {
                mma_tf32(cacc[0][tl], al0[0], al0[1], al0[2], al0[3],
                         __float_as_uint(b[tl].x), __float_as_uint(b[tl].y));
                mma_tf32(cacc[1][tl], al1[0], al1[1], al1[2], al1[3],
                         __float_as_uint(b[tl].x), __float_as_uint(b[tl].y));
            }
        }
    }
    __syncthreads();   // all xs reads done; reuse smem as hs tile

    // Stage C fragments into hs[l][f]
    {
        #pragma unroll
        for (int h = 0; h < 2; h++) {
            const int pr0 = h * 16 + g;
            #pragma unroll
            for (int tl = 0; tl < 4; tl++) {
                const int fc = wid * 32 + tl * 8 + t * 2;
                *(float2*)&hs[pr0 * 256 + fc]       = make_float2(cacc[h][tl][0], cacc[h][tl][1]);
                *(float2*)&hs[(pr0 + 8) * 256 + fc] = make_float2(cacc[h][tl][2], cacc[h][tl][3]);
            }
        }
    }
    __syncthreads();

    // Bias add (per-thread f view), keep acc in regs, rewrite hs for stats
    float acc[TP];
    {
        const float bf = bias[f];
        #pragma unroll
        for (int p = 0; p < TP; p++) {
            acc[p] = hs[p * 256 + f] + bf;
            hs[p * 256 + f] = acc[p];
        }
    }
    __syncthreads();

    // LayerNorm over f (256) per position p: warp-parallel reductions
    {
        #pragma unroll
        for (int rr = 0; rr < 4; rr++) {
            int r = wid * 4 + rr;
            float s = 0.f, s2 = 0.f;
            #pragma unroll
            for (int c0 = 0; c0 < 256; c0 += 32) {
                float v = hs[r * 256 + c0 + lane];
                s += v; s2 += v * v;
            }
            #pragma unroll
            for (int o = 16; o; o >>= 1) {
                s  += __shfl_xor_sync(0xFFFFFFFFu, s,  o);
                s2 += __shfl_xor_sync(0xFFFFFFFFu, s2, o);
            }
            if (lane == 0) {
                float mu = s * (1.f / 256.f);
                float var = s2 * (1.f / 256.f) - mu * mu;
                mu_s[r] = mu;
                rs_s[r] = rsqrtf(var + 1e-5f);
            }
        }
    }
    __syncthreads();

    if (STAGE == 0) {
        const float gg = gamma[f], bb = beta[f];
        #pragma unroll
        for (int p = 0; p < TP; p++) {
            float v = fmaxf((acc[p] - mu_s[p]) * rs_s[p] * gg + bb, 0.f);
            g_h1[(n * LL + l0 + p) * DD + f] = v;
        }
    } else {
        // Fused linear head: prod[p][f] = relu(LN(h)) * lin_w[f], reduce over f.
        const float gg = gamma[f], bb = beta[f];
        const float lw = lin_w[f];
        #pragma unroll
        for (int p = 0; p < TP; p++) {
            float v = fmaxf((acc[p] - mu_s[p]) * rs_s[p] * gg + bb, 0.f);
            hs[p * 256 + f] = v * lw;
        }
        __syncthreads();
        {
            const float lb = lin_b[0];
            #pragma unroll
            for (int rr = 0; rr < 4; rr++) {
                int r = wid * 4 + rr;
                float s = 0.f;
                #pragma unroll
                for (int c0 = 0; c0 < 256; c0 += 32)
                    s += hs[r * 256 + c0 + lane];
                #pragma unroll
                for (int o = 16; o; o >>= 1)
                    s += __shfl_xor_sync(0xFFFFFFFFu, s, o);
                if (lane == 0) {
                    float dpo = fmaxf(s + lb, 0.f);
                    g_dur[n * LL + l0 + r] = (int)(dpo + 0.5f);
                }
            }
        }
    }
}

// ---------------------------------------------------------------------------
// Inclusive scan of durations per row + t -> l binary-search map.
// ---------------------------------------------------------------------------
__global__ void __launch_bounds__(512) scan_map_kernel()
{
    const int n = blockIdx.x;
    const int l = threadIdx.x;

    __shared__ int sc[LL];
    sc[l] = g_dur[n * LL + l];
    __syncthreads();
    for (int off = 1; off < LL; off <<= 1) {
        int v = (l >= off) ? sc[l - off] : 0;
        __syncthreads();
        sc[l] += v;
        __syncthreads();
    }

    const int total = sc[LL - 1];
    for (int t = l; t < TT; t += LL) {
        int res = -1;
        if (t < total) {
            int lo = 0, hi = LL - 1;
            while (lo < hi) {
                int mid = (lo + hi) >> 1;
                if (sc[mid] > t) hi = mid; else lo = mid + 1;
            }
            res = lo;
        }
        g_lmap[n * TT + t] = res;
    }
}

// ---------------------------------------------------------------------------
// out[n, t, :] = x[n, lmap[n,t], :]  (or zeros), grid-stride (8 float4/thread)
// + fused tail (WVF_pos = 1..TT). 2048 blocks.
// ---------------------------------------------------------------------------
#define EXP_BLOCKS 2048
__global__ void __launch_bounds__(256) expand_copy_kernel(
    const float* __restrict__ x,
    float* __restrict__ out,
    int tail)
{
    const int nthreads = EXP_BLOCKS * 256;
    const int tid0 = blockIdx.x * 256 + threadIdx.x;

    #pragma unroll
    for (int k = 0; k < 8; k++) {
        const int idx = tid0 + k * nthreads;       // over NB*TT*64 float4
        const int c = idx & 63;
        const int t = (idx >> 6) & (TT - 1);
        const int n = idx >> 18;
        const int l = g_lmap[n * TT + t];
        float4 v = make_float4(0.f, 0.f, 0.f, 0.f);
        if (l >= 0) v = ((const float4*)x)[(n * LL + l) * (DD / 4) + c];
        ((float4*)out)[idx] = v;
    }

    for (int i = tid0; i < tail; i += nthreads)
        out[NB * TT * DD + i] = (float)((i % TT) + 1);
}

extern "C" void kernel_launch(void* const* d_in, const int* in_sizes, int n_in,
                              void* d_out, int out_size)
{
    const float* x       = (const float*)d_in[0];
    const float* conv1_w = (const float*)d_in[1];
    const float* conv1_b = (const float*)d_in[2];
    const float* ln1_g   = (const float*)d_in[3];
    const float* ln1_b   = (const float*)d_in[4];
    const float* conv2_w = (const float*)d_in[5];
    const float* conv2_b = (const float*)d_in[6];
    const float* ln2_g   = (const float*)d_in[7];
    const float* ln2_b   = (const float*)d_in[8];
    const float* lin_w   = (const float*)d_in[9];
    const float* lin_b   = (const float*)d_in[10];

    float* out = (float*)d_out;

    // Opt-in to >48KB dynamic smem (idempotent; capture-safe; not an allocation).
    static bool attr_done = false;
    if (!attr_done) {
        cudaFuncSetAttribute(conv_ln_relu_kernel<0>,
                             cudaFuncAttributeMaxDynamicSharedMemorySize, SMEM_BYTES);
        cudaFuncSetAttribute(conv_ln_relu_kernel<1>,
                             cudaFuncAttributeMaxDynamicSharedMemorySize, SMEM_BYTES);
        attr_done = true;
    }

    pack_wf_kernel<<<2 * 3 * 32, 1024>>>(conv1_w, conv2_w);

    const int conv_grid = NB * (LL / TP);   // 256
    conv_ln_relu_kernel<0><<<conv_grid, 256, SMEM_BYTES>>>(x, conv1_b, ln1_g, ln1_b, lin_w, lin_b);
    conv_ln_relu_kernel<1><<<conv_grid, 256, SMEM_BYTES>>>(x, conv2_b, ln2_g, ln2_b, lin_w, lin_b);
    scan_map_kernel<<<NB, LL>>>();

    const int main_elems = NB * TT * DD;
    int tail = out_size - main_elems;
    if (tail < 0) tail = 0;
    expand_copy_kernel<<<EXP_BLOCKS, 256>>>(x, out, tail);
}